// round 7
// baseline (speedup 1.0000x reference)
#include <cuda_runtime.h>

#define NG   4096
#define HH   128
#define WW   128
#define NPIX (HH*WW)
#define EPSF 1e-6f
#define LOG2E 1.4426950408889634f
#define SXY  31.75f   // (128-1)/2 * 0.5
#define OFFC 63.5f
#define GPB  128      // gaussians per chunk
#define NCHUNK (NG/GPB)
#define NXB  (NPIX/1024)   // 16 pixel-blocks (1024 px each)

// Per-chunk partial images (written fully every launch; no zeroing needed)
__device__ float g_partial[NCHUNK * NPIX];
__device__ float g_blockmax[NXB];

typedef unsigned long long u64;

__device__ __forceinline__ u64 pack2(float a, float b) {
    u64 r; asm("mov.b64 %0, {%1, %2};" : "=l"(r) : "f"(a), "f"(b)); return r;
}
__device__ __forceinline__ u64 fma2(u64 a, u64 b, u64 c) {
    u64 d; asm("fma.rn.f32x2 %0, %1, %2, %3;" : "=l"(d) : "l"(a), "l"(b), "l"(c)); return d;
}
__device__ __forceinline__ u64 add2(u64 a, u64 b) {
    u64 d; asm("add.rn.f32x2 %0, %1, %2;" : "=l"(d) : "l"(a), "l"(b)); return d;
}
__device__ __forceinline__ void unpack2(float& lo, float& hi, u64 v) {
    asm("mov.b64 {%0, %1}, %2;" : "=f"(lo), "=f"(hi) : "l"(v));
}
__device__ __forceinline__ float ex2(float x) {
    float r; asm("ex2.approx.ftz.f32 %0, %1;" : "=f"(r) : "f"(x)); return r;
}
__device__ __forceinline__ u64 ex2_2(u64 v) {
    float lo, hi; unpack2(lo, hi, v);
    return pack2(ex2(lo), ex2(hi));
}

// Per-gaussian projection -> expanded quadratic coefficients, written to smem.
// sc layout (pair-interleaved): pair p holds [A0,A1,B0,B1,C0,C1,D0,D1,E0,E1,F0,F1]
__device__ __forceinline__ void prep_one(int n, int li, float* sc,
                                         const float* __restrict__ means,
                                         const float* __restrict__ raw_scales,
                                         const float* __restrict__ rotors,
                                         float t, float angle)
{
    float r[8];
#pragma unroll
    for (int i = 0; i < 8; i++) r[i] = rotors[8*n + i];

    float q1w = r[0], q1x = r[4], q1y = r[5], q1z = r[6];
    {
        float n2 = q1w*q1w + q1x*q1x + q1y*q1y + q1z*q1z;
        float inv = rsqrtf(fmaxf(n2, 1e-24f));
        q1w *= inv; q1x *= inv; q1y *= inv; q1z *= inv;
    }
    float q2w = r[7], q2x = -r[1], q2y = -r[2], q2z = -r[3];
    {
        float n2 = q2w*q2w + q2x*q2x + q2y*q2y + q2z*q2z;
        float inv = rsqrtf(fmaxf(n2, 1e-24f));
        q2w *= inv; q2x *= inv; q2y *= inv; q2z *= inv;
    }

    float L[4][4]  = {{q1w,-q1x,-q1y,-q1z},
                      {q1x, q1w,-q1z, q1y},
                      {q1y, q1z, q1w,-q1x},
                      {q1z,-q1y, q1x, q1w}};
    float Rm[4][4] = {{ q2w, q2x, q2y, q2z},
                      {-q2x, q2w, q2z,-q2y},
                      {-q2y,-q2z, q2w, q2x},
                      {-q2z, q2y,-q2x, q2w}};
    float R4[4][4];
#pragma unroll
    for (int i = 0; i < 4; i++)
#pragma unroll
        for (int k = 0; k < 4; k++)
            R4[i][k] = L[i][0]*Rm[0][k] + L[i][1]*Rm[1][k]
                     + L[i][2]*Rm[2][k] + L[i][3]*Rm[3][k];

    float s2[4];
#pragma unroll
    for (int j = 0; j < 4; j++) s2[j] = __expf(2.f * raw_scales[4*n + j]);

    float cov[4][4];
#pragma unroll
    for (int i = 0; i < 4; i++)
#pragma unroll
        for (int k = i; k < 4; k++)
            cov[i][k] = R4[i][0]*s2[0]*R4[k][0] + R4[i][1]*s2[1]*R4[k][1]
                      + R4[i][2]*s2[2]*R4[k][2] + R4[i][3]*s2[3]*R4[k][3];

    float Wm   = fmaxf(cov[3][3], EPSF);
    float invW = __fdividef(1.f, Wm);
    float td   = t - means[4*n + 3];

    float mx = means[4*n+0] + cov[0][3] * td * invW;
    float my = means[4*n+1] + cov[1][3] * td * invW;
    float mz = means[4*n+2] + cov[2][3] * td * invW;

    float ca = __cosf(angle), sa = __sinf(angle);
    float mvx = ca*mx + sa*mz;
    float mvy = my;

    float M00 = cov[0][0] - cov[0][3]*cov[0][3]*invW;
    float M01 = cov[0][1] - cov[0][3]*cov[1][3]*invW;
    float M02 = cov[0][2] - cov[0][3]*cov[2][3]*invW;
    float M11 = cov[1][1] - cov[1][3]*cov[1][3]*invW;
    float M12 = cov[1][2] - cov[1][3]*cov[2][3]*invW;

    float c00 = ca*ca*M00 + 2.f*ca*sa*M02 + sa*sa*(cov[2][2] - cov[2][3]*cov[2][3]*invW);
    float c01 = ca*M01 + sa*M12;
    float c11 = M11;

    float a = SXY*SXY*c00 + EPSF;
    float b = SXY*SXY*c01;
    float d = SXY*SXY*c11 + EPSF;
    float invdet = __fdividef(1.f, a*d - b*b);

    float mux = SXY*mvx + OFFC;
    float muy = SXY*mvy + OFFC;

    float A  = -0.5f * LOG2E * d * invdet;
    float B  =         LOG2E * b * invdet;
    float C  = -0.5f * LOG2E * a * invdet;
    float lw = -0.5f * td * td * invW * LOG2E;

    float D_ = -2.f*A*mux - B*muy;
    float E_ = -2.f*C*muy - B*mux;
    float F_ = A*mux*mux + B*mux*muy + C*muy*muy + lw;

    float* dst = sc + 12*(li >> 1) + (li & 1);
    dst[0]  = A;
    dst[2]  = B;
    dst[4]  = C;
    dst[6]  = D_;
    dst[8]  = E_;
    dst[10] = F_;
}

// Fused render: block = (xb, chunk). Threads 0-127 prep the chunk's 128
// gaussians into smem; then all 256 threads render 1024 pixels (4 rows each
// via forward differences). Results stored (plain STG) to g_partial.
__global__ void __launch_bounds__(256) render_kernel(
    const float* __restrict__ means,
    const float* __restrict__ raw_scales,
    const float* __restrict__ rotors,
    const float* __restrict__ t_ptr,
    const float* __restrict__ angle_ptr)
{
    __shared__ float sc[GPB/2 * 12];   // 3 KB

    if (threadIdx.x < GPB) {
        float t     = *t_ptr;
        float angle = *angle_ptr;
        int n = blockIdx.y * GPB + threadIdx.x;
        prep_one(n, threadIdx.x, sc, means, raw_scales, rotors, t, angle);
    }
    __syncthreads();

    int x  = threadIdx.x & (WW - 1);
    int y0 = blockIdx.x * 8 + ((threadIdx.x >> 7) << 2);
    float xf = (float)x;
    float yf = (float)y0;

    u64 X2   = pack2(xf*xf, xf*xf);
    u64 XY   = pack2(xf*yf, xf*yf);
    u64 Y2   = pack2(yf*yf, yf*yf);
    u64 Xp   = pack2(xf, xf);
    u64 Yp   = pack2(yf, yf);
    u64 Y2p1 = pack2(2.f*yf + 1.f, 2.f*yf + 1.f);

    u64 s0 = 0, s1 = 0, s2 = 0, s3 = 0;
    const ulonglong2* cp = (const ulonglong2*)sc;
#pragma unroll 4
    for (int g = 0; g < GPB/2; g++) {
        ulonglong2 u0 = cp[3*g + 0];   // {A, B}
        ulonglong2 u1 = cp[3*g + 1];   // {C, D}
        ulonglong2 u2 = cp[3*g + 2];   // {E, F}

        u64 e0 = u2.y;
        e0 = fma2(u0.x, X2, e0);
        e0 = fma2(u0.y, XY, e0);
        e0 = fma2(u1.x, Y2, e0);
        e0 = fma2(u1.y, Xp, e0);
        e0 = fma2(u2.x, Yp, e0);

        // forward differences along y: d1 = B*x + C*(2y+1) + E, d2 = 2C
        u64 G  = fma2(u0.y, Xp, fma2(u1.x, Y2p1, u2.x));
        u64 C2 = add2(u1.x, u1.x);
        u64 e1 = add2(e0, G);
        u64 H  = add2(G, C2);
        u64 e2 = add2(e1, H);
        u64 H2 = add2(H, C2);
        u64 e3 = add2(e2, H2);

        s0 = add2(s0, ex2_2(e0));
        s1 = add2(s1, ex2_2(e1));
        s2 = add2(s2, ex2_2(e2));
        s3 = add2(s3, ex2_2(e3));
    }

    float* dst = g_partial + blockIdx.y * NPIX;
    float lo, hi;
    unpack2(lo, hi, s0); dst[(y0+0)*WW + x] = lo + hi;
    unpack2(lo, hi, s1); dst[(y0+1)*WW + x] = lo + hi;
    unpack2(lo, hi, s2); dst[(y0+2)*WW + x] = lo + hi;
    unpack2(lo, hi, s3); dst[(y0+3)*WW + x] = lo + hi;
}

// Sum the NCHUNK partial images into out, record per-block max.
__global__ void __launch_bounds__(256) reduce_kernel(float* __restrict__ out)
{
    __shared__ float smax[8];
    int p4 = blockIdx.x * 256 + threadIdx.x;     // float4 index

    float4 acc = ((const float4*)g_partial)[p4];
#pragma unroll
    for (int c = 1; c < NCHUNK; c++) {
        float4 v = ((const float4*)(g_partial + c * NPIX))[p4];
        acc.x += v.x; acc.y += v.y; acc.z += v.z; acc.w += v.w;
    }
    ((float4*)out)[p4] = acc;

    float m = fmaxf(fmaxf(acc.x, acc.y), fmaxf(acc.z, acc.w));
#pragma unroll
    for (int o = 16; o; o >>= 1)
        m = fmaxf(m, __shfl_xor_sync(0xFFFFFFFFu, m, o));
    if ((threadIdx.x & 31) == 0) smax[threadIdx.x >> 5] = m;
    __syncthreads();
    if (threadIdx.x == 0) {
        float bm = smax[0];
#pragma unroll
        for (int i = 1; i < 8; i++) bm = fmaxf(bm, smax[i]);
        g_blockmax[blockIdx.x] = bm;
    }
}

// Broadcast global max, scale.
__global__ void __launch_bounds__(256) scale_kernel(float* __restrict__ out)
{
    float m = g_blockmax[0];
#pragma unroll
    for (int i = 1; i < NXB; i++) m = fmaxf(m, g_blockmax[i]);
    float inv = __fdividef(1.f, fmaxf(m, EPSF));

    int p4 = blockIdx.x * 256 + threadIdx.x;
    float4 v = ((const float4*)out)[p4];
    v.x *= inv; v.y *= inv; v.z *= inv; v.w *= inv;
    ((float4*)out)[p4] = v;
}

extern "C" void kernel_launch(void* const* d_in, const int* in_sizes, int n_in,
                              void* d_out, int out_size)
{
    const float* means      = (const float*)d_in[0];
    const float* raw_scales = (const float*)d_in[1];
    const float* rotors     = (const float*)d_in[2];
    const float* t_ptr      = (const float*)d_in[3];
    const float* angle_ptr  = (const float*)d_in[4];
    float* out = (float*)d_out;

    render_kernel<<<dim3(NXB, NCHUNK), 256>>>(means, raw_scales, rotors, t_ptr, angle_ptr);
    reduce_kernel<<<NPIX/4/256, 256>>>(out);
    scale_kernel<<<NPIX/4/256, 256>>>(out);
}

// round 8
// speedup vs baseline: 1.1939x; 1.1939x over previous
#include <cuda_runtime.h>

#define NG   4096
#define HH   128
#define WW   128
#define NPIX (HH*WW)
#define EPSF 1e-6f
#define LOG2E 1.4426950408889634f
#define SXY  31.75f   // (128-1)/2 * 0.5
#define OFFC 63.5f
#define GPB  64       // gaussians per chunk
#define NCHUNK (NG/GPB)
#define NXB  (NPIX/1024)   // 16 pixel-blocks (1024 px each)

// Accumulator image. Zero-initialized at module load; finalize_kernel re-zeros
// it at the end of every launch, so each replay sees zeros.
__device__ float g_accum[NPIX];

typedef unsigned long long u64;

__device__ __forceinline__ u64 pack2(float a, float b) {
    u64 r; asm("mov.b64 %0, {%1, %2};" : "=l"(r) : "f"(a), "f"(b)); return r;
}
__device__ __forceinline__ u64 fma2(u64 a, u64 b, u64 c) {
    u64 d; asm("fma.rn.f32x2 %0, %1, %2, %3;" : "=l"(d) : "l"(a), "l"(b), "l"(c)); return d;
}
__device__ __forceinline__ u64 add2(u64 a, u64 b) {
    u64 d; asm("add.rn.f32x2 %0, %1, %2;" : "=l"(d) : "l"(a), "l"(b)); return d;
}
__device__ __forceinline__ void unpack2(float& lo, float& hi, u64 v) {
    asm("mov.b64 {%0, %1}, %2;" : "=f"(lo), "=f"(hi) : "l"(v));
}
__device__ __forceinline__ float ex2(float x) {
    float r; asm("ex2.approx.ftz.f32 %0, %1;" : "=f"(r) : "f"(x)); return r;
}
__device__ __forceinline__ u64 ex2_2(u64 v) {
    float lo, hi; unpack2(lo, hi, v);
    return pack2(ex2(lo), ex2(hi));
}

// Per-gaussian projection -> expanded quadratic coefficients, written to smem.
// sc layout (pair-interleaved): pair p holds [A0,A1,B0,B1,C0,C1,D0,D1,E0,E1,F0,F1]
__device__ __forceinline__ void prep_one(int n, int li, float* sc,
                                         const float* __restrict__ means,
                                         const float* __restrict__ raw_scales,
                                         const float* __restrict__ rotors,
                                         float t, float angle)
{
    float r[8];
#pragma unroll
    for (int i = 0; i < 8; i++) r[i] = rotors[8*n + i];

    float q1w = r[0], q1x = r[4], q1y = r[5], q1z = r[6];
    {
        float n2 = q1w*q1w + q1x*q1x + q1y*q1y + q1z*q1z;
        float inv = rsqrtf(fmaxf(n2, 1e-24f));
        q1w *= inv; q1x *= inv; q1y *= inv; q1z *= inv;
    }
    float q2w = r[7], q2x = -r[1], q2y = -r[2], q2z = -r[3];
    {
        float n2 = q2w*q2w + q2x*q2x + q2y*q2y + q2z*q2z;
        float inv = rsqrtf(fmaxf(n2, 1e-24f));
        q2w *= inv; q2x *= inv; q2y *= inv; q2z *= inv;
    }

    float L[4][4]  = {{q1w,-q1x,-q1y,-q1z},
                      {q1x, q1w,-q1z, q1y},
                      {q1y, q1z, q1w,-q1x},
                      {q1z,-q1y, q1x, q1w}};
    float Rm[4][4] = {{ q2w, q2x, q2y, q2z},
                      {-q2x, q2w, q2z,-q2y},
                      {-q2y,-q2z, q2w, q2x},
                      {-q2z, q2y,-q2x, q2w}};
    float R4[4][4];
#pragma unroll
    for (int i = 0; i < 4; i++)
#pragma unroll
        for (int k = 0; k < 4; k++)
            R4[i][k] = L[i][0]*Rm[0][k] + L[i][1]*Rm[1][k]
                     + L[i][2]*Rm[2][k] + L[i][3]*Rm[3][k];

    float s2[4];
#pragma unroll
    for (int j = 0; j < 4; j++) s2[j] = __expf(2.f * raw_scales[4*n + j]);

    float cov[4][4];
#pragma unroll
    for (int i = 0; i < 4; i++)
#pragma unroll
        for (int k = i; k < 4; k++)
            cov[i][k] = R4[i][0]*s2[0]*R4[k][0] + R4[i][1]*s2[1]*R4[k][1]
                      + R4[i][2]*s2[2]*R4[k][2] + R4[i][3]*s2[3]*R4[k][3];

    float Wm   = fmaxf(cov[3][3], EPSF);
    float invW = __fdividef(1.f, Wm);
    float td   = t - means[4*n + 3];

    float mx = means[4*n+0] + cov[0][3] * td * invW;
    float my = means[4*n+1] + cov[1][3] * td * invW;
    float mz = means[4*n+2] + cov[2][3] * td * invW;

    float ca = __cosf(angle), sa = __sinf(angle);
    float mvx = ca*mx + sa*mz;
    float mvy = my;

    float M00 = cov[0][0] - cov[0][3]*cov[0][3]*invW;
    float M01 = cov[0][1] - cov[0][3]*cov[1][3]*invW;
    float M02 = cov[0][2] - cov[0][3]*cov[2][3]*invW;
    float M11 = cov[1][1] - cov[1][3]*cov[1][3]*invW;
    float M12 = cov[1][2] - cov[1][3]*cov[2][3]*invW;

    float c00 = ca*ca*M00 + 2.f*ca*sa*M02 + sa*sa*(cov[2][2] - cov[2][3]*cov[2][3]*invW);
    float c01 = ca*M01 + sa*M12;
    float c11 = M11;

    float a = SXY*SXY*c00 + EPSF;
    float b = SXY*SXY*c01;
    float d = SXY*SXY*c11 + EPSF;
    float invdet = __fdividef(1.f, a*d - b*b);

    float mux = SXY*mvx + OFFC;
    float muy = SXY*mvy + OFFC;

    float A  = -0.5f * LOG2E * d * invdet;
    float B  =         LOG2E * b * invdet;
    float C  = -0.5f * LOG2E * a * invdet;
    float lw = -0.5f * td * td * invW * LOG2E;

    float D_ = -2.f*A*mux - B*muy;
    float E_ = -2.f*C*muy - B*mux;
    float F_ = A*mux*mux + B*mux*muy + C*muy*muy + lw;

    float* dst = sc + 12*(li >> 1) + (li & 1);
    dst[0]  = A;
    dst[2]  = B;
    dst[4]  = C;
    dst[6]  = D_;
    dst[8]  = E_;
    dst[10] = F_;
}

// Fused render: block = (xb, chunk). Threads 0..GPB-1 prep the chunk's
// gaussians into smem; then all 256 threads render 1024 pixels (4 rows each
// via forward differences). Partial sums REDG-added into g_accum.
__global__ void __launch_bounds__(256) render_kernel(
    const float* __restrict__ means,
    const float* __restrict__ raw_scales,
    const float* __restrict__ rotors,
    const float* __restrict__ t_ptr,
    const float* __restrict__ angle_ptr)
{
    __shared__ float sc[GPB/2 * 12];   // 1.5 KB

    if (threadIdx.x < GPB) {
        float t     = *t_ptr;
        float angle = *angle_ptr;
        int n = blockIdx.y * GPB + threadIdx.x;
        prep_one(n, threadIdx.x, sc, means, raw_scales, rotors, t, angle);
    }
    __syncthreads();

    int x  = threadIdx.x & (WW - 1);
    int y0 = blockIdx.x * 8 + ((threadIdx.x >> 7) << 2);
    float xf = (float)x;
    float yf = (float)y0;

    u64 X2   = pack2(xf*xf, xf*xf);
    u64 XY   = pack2(xf*yf, xf*yf);
    u64 Y2   = pack2(yf*yf, yf*yf);
    u64 Xp   = pack2(xf, xf);
    u64 Yp   = pack2(yf, yf);
    u64 Y2p1 = pack2(2.f*yf + 1.f, 2.f*yf + 1.f);

    u64 s0 = 0, s1 = 0, s2 = 0, s3 = 0;
    const ulonglong2* cp = (const ulonglong2*)sc;
#pragma unroll 4
    for (int g = 0; g < GPB/2; g++) {
        ulonglong2 u0 = cp[3*g + 0];   // {A, B}
        ulonglong2 u1 = cp[3*g + 1];   // {C, D}
        ulonglong2 u2 = cp[3*g + 2];   // {E, F}

        u64 e0 = u2.y;
        e0 = fma2(u0.x, X2, e0);
        e0 = fma2(u0.y, XY, e0);
        e0 = fma2(u1.x, Y2, e0);
        e0 = fma2(u1.y, Xp, e0);
        e0 = fma2(u2.x, Yp, e0);

        // forward differences along y: d1 = B*x + C*(2y+1) + E, d2 = 2C
        u64 G  = fma2(u0.y, Xp, fma2(u1.x, Y2p1, u2.x));
        u64 C2 = add2(u1.x, u1.x);
        u64 e1 = add2(e0, G);
        u64 H  = add2(G, C2);
        u64 e2 = add2(e1, H);
        u64 H2 = add2(H, C2);
        u64 e3 = add2(e2, H2);

        s0 = add2(s0, ex2_2(e0));
        s1 = add2(s1, ex2_2(e1));
        s2 = add2(s2, ex2_2(e2));
        s3 = add2(s3, ex2_2(e3));
    }

    float lo, hi;
    unpack2(lo, hi, s0); atomicAdd(&g_accum[(y0+0)*WW + x], lo + hi);
    unpack2(lo, hi, s1); atomicAdd(&g_accum[(y0+1)*WW + x], lo + hi);
    unpack2(lo, hi, s2); atomicAdd(&g_accum[(y0+2)*WW + x], lo + hi);
    unpack2(lo, hi, s3); atomicAdd(&g_accum[(y0+3)*WW + x], lo + hi);
}

// Single block: global max over g_accum, write normalized image to out,
// then re-zero g_accum for the next launch.
__global__ void __launch_bounds__(1024) finalize_kernel(float* __restrict__ out)
{
    __shared__ float smax[32];
    float4* a4 = (float4*)g_accum;
    float4 v[NPIX/4/1024];                 // 4 float4 per thread
    float m = 0.f;
#pragma unroll
    for (int i = 0; i < NPIX/4/1024; i++) {
        v[i] = a4[threadIdx.x + i * 1024];
        m = fmaxf(m, fmaxf(fmaxf(v[i].x, v[i].y), fmaxf(v[i].z, v[i].w)));
    }
#pragma unroll
    for (int o = 16; o; o >>= 1)
        m = fmaxf(m, __shfl_xor_sync(0xFFFFFFFFu, m, o));
    if ((threadIdx.x & 31) == 0) smax[threadIdx.x >> 5] = m;
    __syncthreads();
    if (threadIdx.x < 32) {
        m = smax[threadIdx.x];
#pragma unroll
        for (int o = 16; o; o >>= 1)
            m = fmaxf(m, __shfl_xor_sync(0xFFFFFFFFu, m, o));
        if (threadIdx.x == 0) smax[0] = fmaxf(m, EPSF);
    }
    __syncthreads();
    float inv = __fdividef(1.f, smax[0]);

    float4* o4 = (float4*)out;
    const float4 z = make_float4(0.f, 0.f, 0.f, 0.f);
#pragma unroll
    for (int i = 0; i < NPIX/4/1024; i++) {
        float4 w = v[i];
        w.x *= inv; w.y *= inv; w.z *= inv; w.w *= inv;
        o4[threadIdx.x + i * 1024] = w;
        a4[threadIdx.x + i * 1024] = z;    // reset accumulator for next launch
    }
}

extern "C" void kernel_launch(void* const* d_in, const int* in_sizes, int n_in,
                              void* d_out, int out_size)
{
    const float* means      = (const float*)d_in[0];
    const float* raw_scales = (const float*)d_in[1];
    const float* rotors     = (const float*)d_in[2];
    const float* t_ptr      = (const float*)d_in[3];
    const float* angle_ptr  = (const float*)d_in[4];
    float* out = (float*)d_out;

    render_kernel<<<dim3(NXB, NCHUNK), 256>>>(means, raw_scales, rotors, t_ptr, angle_ptr);
    finalize_kernel<<<1, 1024>>>(out);
}